// round 16
// baseline (speedup 1.0000x reference)
#include <cuda_runtime.h>
#include <cuda_bf16.h>
#include <cstdint>

#define N_DAGS 16384
#define NPAIR  (N_DAGS / 2)
#define NN     48
#define DF     62
#define NCLS   500
#define K2B    256

typedef unsigned long long ull;

// ---------------- scratch ----------------
__device__ float g_pre [(size_t)N_DAGS * NN * 64];   // atomP + b_merge, 64-padded
__device__ float g_last [N_DAGS * 64];
__device__ float g_score[N_DAGS];
__device__ float g_partP[K2B * 64];
__device__ float g_partS[K2B];
__device__ float g_partM[K2B];
__device__ unsigned g_ctr;

// ---------------- packed f32x2 helpers ----------------
__device__ __forceinline__ ull ffma2(ull a, ull b, ull c) {
    ull d;
    asm("fma.rn.f32x2 %0, %1, %2, %3;" : "=l"(d) : "l"(a), "l"(b), "l"(c));
    return d;
}
__device__ __forceinline__ ull pack2(float a, float b) {
    return (ull)__float_as_uint(a) | ((ull)__float_as_uint(b) << 32);
}
__device__ __forceinline__ float lo2(ull v) { return __uint_as_float((unsigned)v); }
__device__ __forceinline__ float hi2(ull v) { return __uint_as_float((unsigned)(v >> 32)); }

__device__ __forceinline__ float warp_sum(float v) {
    #pragma unroll
    for (int o = 16; o > 0; o >>= 1) v += __shfl_xor_sync(0xffffffffu, v, o);
    return v;
}
__device__ __forceinline__ float red8(float v) {
    v += __shfl_xor_sync(0xffffffffu, v, 4);
    v += __shfl_xor_sync(0xffffffffu, v, 2);
    v += __shfl_xor_sync(0xffffffffu, v, 1);
    return v;
}
__device__ __forceinline__ int max4(int4 q) { return max(max(q.x, q.y), max(q.z, q.w)); }
__device__ __forceinline__ bool mbit(unsigned bl, unsigned bh, int t) {
    return (t < 32) ? ((bl >> t) & 1u) : ((bh >> (t - 32)) & 1u);
}

// ---------------- mma helpers (bf16 m16n8k16) ----------------
__device__ __forceinline__ uint32_t smem_u32(const void* p) {
    return (uint32_t)__cvta_generic_to_shared(p);
}
__device__ __forceinline__ void ldm_x4(unsigned r[4], uint32_t addr) {
    asm volatile("ldmatrix.sync.aligned.m8n8.x4.shared.b16 {%0,%1,%2,%3}, [%4];"
        : "=r"(r[0]), "=r"(r[1]), "=r"(r[2]), "=r"(r[3]) : "r"(addr));
}
__device__ __forceinline__ void ldm_x2t(unsigned r[2], uint32_t addr) {
    asm volatile("ldmatrix.sync.aligned.m8n8.x2.trans.shared.b16 {%0,%1}, [%2];"
        : "=r"(r[0]), "=r"(r[1]) : "r"(addr));
}
__device__ __forceinline__ void mma16816(float d[4], const unsigned a[4], const unsigned b[2]) {
    asm volatile("mma.sync.aligned.m16n8k16.row.col.f32.bf16.bf16.f32 "
        "{%0,%1,%2,%3}, {%4,%5,%6,%7}, {%8,%9}, {%0,%1,%2,%3};"
        : "+f"(d[0]), "+f"(d[1]), "+f"(d[2]), "+f"(d[3])
        : "r"(a[0]), "r"(a[1]), "r"(a[2]), "r"(a[3]), "r"(b[0]), "r"(b[1]));
}

// =================================================================
// k_zero: reset the work-stealing counter
// =================================================================
__global__ void k_zero() { g_ctr = 0u; }

// =================================================================
// k_pre: g_pre[node][g] = sum_f Wm[g][62+f]*atoms[node][f] + bm[g]
// Split-bf16 3-product GEMM. 4 row-tiles per block (W staged once).
// =================================================================
#define PSTRIDE 72

__global__ void __launch_bounds__(128)
k_pre(const float* __restrict__ atoms, const float* __restrict__ Wm,
      const float* __restrict__ bm) {
    __shared__ __align__(16) __nv_bfloat16 sAh[64 * PSTRIDE];
    __shared__ __align__(16) __nv_bfloat16 sAl[64 * PSTRIDE];
    __shared__ __align__(16) __nv_bfloat16 sWh[64 * PSTRIDE];
    __shared__ __align__(16) __nv_bfloat16 sWl[64 * PSTRIDE];
    __shared__ float sBm[64];

    const int tid = threadIdx.x, lane = tid & 31, warp = tid >> 5;

    for (int i = tid; i < 64 * 64; i += 128) {
        int f = i >> 6, g = i & 63;
        float w = (f < DF && g < DF) ? __ldg(&Wm[g * 124 + DF + f]) : 0.f;
        __nv_bfloat16 h = __float2bfloat16(w);
        sWh[f * PSTRIDE + g] = h;
        sWl[f * PSTRIDE + g] = __float2bfloat16(w - __bfloat162float(h));
    }
    if (tid < 64) sBm[tid] = (tid < DF) ? __ldg(&bm[tid]) : 0.f;

    #pragma unroll 1
    for (int tile = 0; tile < 4; tile++) {
        const size_t row0 = (size_t)blockIdx.x * 256 + (size_t)tile * 64;
        __syncthreads();

        for (int i = tid; i < 64 * 64; i += 128) {
            int r = i >> 6, c = i & 63;
            float a = (c < DF) ? __ldg(&atoms[(row0 + r) * DF + c]) : 0.f;
            __nv_bfloat16 h = __float2bfloat16(a);
            sAh[r * PSTRIDE + c] = h;
            sAl[r * PSTRIDE + c] = __float2bfloat16(a - __bfloat162float(h));
        }
        __syncthreads();

        unsigned ah[4][4], al[4][4];
        {
            uint32_t aoff = ((warp * 16 + (lane & 15)) * PSTRIDE) * 2 + (lane >> 4) * 16;
            uint32_t aH = smem_u32(sAh) + aoff, aL = smem_u32(sAl) + aoff;
            #pragma unroll
            for (int k = 0; k < 4; k++) {
                ldm_x4(ah[k], aH + k * 32);
                ldm_x4(al[k], aL + k * 32);
            }
        }

        const uint32_t bRow = (lane & 15) * (PSTRIDE * 2);
        #pragma unroll
        for (int n = 0; n < 8; n++) {
            float d[4] = {0.f, 0.f, 0.f, 0.f};
            #pragma unroll
            for (int k = 0; k < 4; k++) {
                unsigned bh[2], blo[2];
                uint32_t boff = (uint32_t)(k * 16 * PSTRIDE * 2) + bRow + n * 16;
                ldm_x2t(bh,  smem_u32(sWh) + boff);
                ldm_x2t(blo, smem_u32(sWl) + boff);
                mma16816(d, ah[k], bh);
                mma16816(d, al[k], bh);
                mma16816(d, ah[k], blo);
            }
            int r = lane >> 2;
            int c = n * 8 + 2 * (lane & 3);
            float b0 = sBm[c], b1 = sBm[c + 1];
            size_t ro = (row0 + warp * 16 + r) * 64 + c;
            *(float2*)&g_pre[ro]           = make_float2(d[0] + b0, d[1] + b1);
            *(float2*)&g_pre[ro + 8 * 64]  = make_float2(d[2] + b0, d[3] + b1);
        }
    }
}

// per-dag smem region: 3520 floats (14080 B); per warp 2 dags
#define RWF    3520
#define W_OUT  0
#define W_XS   3072
#define W_SCB  3136
#define W_PRD  3328
#define DSM_BYTES (8 * RWF * 4)   // 112640 (4 warps x 2 dags)

// =================================================================
// k_dag: recurrent loop. ONE WARP = TWO DAG STREAMS (shared W regs),
// dynamic work-stealing over dag pairs. Thread owns rows (2l, 2l+1).
// =================================================================
__global__ void __launch_bounds__(128, 2)
k_dag(const float* __restrict__ atoms, const int* __restrict__ preds,
      const float* __restrict__ Wm,   const float* __restrict__ Ws,
      const float* __restrict__ bs,   const float* __restrict__ attw,
      const float* __restrict__ dagw) {
    extern __shared__ float DSM[];
    const int tid = threadIdx.x, lane = tid & 31, warp = tid >> 5;
    float* R0   = DSM + warp * (2 * RWF);
    float* R1   = R0 + RWF;
    float* OUT0 = R0 + W_OUT,  * OUT1 = R1 + W_OUT;
    float* XS0  = R0 + W_XS,   * XS1  = R1 + W_XS;
    float* SCB0 = R0 + W_SCB,  * SCB1 = R1 + W_SCB;
    int*   PRD0 = (int*)(R0 + W_PRD), * PRD1 = (int*)(R1 + W_PRD);

    const int r0 = 2 * lane, r1 = 2 * lane + 1;
    const bool a0 = (r0 < DF), a1 = (r1 < DF);
    const float aw0 = a0 ? attw[r0] : 0.f, aw1 = a1 ? attw[r1] : 0.f;

    // x-half merge weights: loaded once, shared by both streams
    ull W[64];
    #pragma unroll
    for (int j = 0; j < 32; j++) {
        W[j]      = (a0 && j < 31) ? pack2(__ldg(&Wm[r0*124 + 2*j]), __ldg(&Wm[r0*124 + 2*j + 1])) : 0ull;
        W[32 + j] = (a1 && j < 31) ? pack2(__ldg(&Wm[r1*124 + 2*j]), __ldg(&Wm[r1*124 + 2*j + 1])) : 0ull;
    }

    #pragma unroll 1
    for (;;) {
        // ---- dynamic ticket: one dag PAIR ----
        int pr;
        if (lane == 0) pr = (int)atomicAdd(&g_ctr, 1u);
        pr = __shfl_sync(0xffffffffu, pr, 0);
        if (pr >= NPAIR) break;
        const int d0 = 2 * pr, d1 = 2 * pr + 1;

        // ---- preds + masks (both streams) ----
        unsigned bl0, bh0, bl1, bh1;
        {
            const int4* P0 = (const int4*)(preds + (size_t)d0 * NN * 4);
            const int4* P1 = (const int4*)(preds + (size_t)d1 * NN * 4);
            int4 q = __ldg(P0 + lane); ((int4*)PRD0)[lane] = q;
            bl0 = __ballot_sync(0xffffffffu, max4(q) >= 0);
            bool h = true;
            if (lane < 16) { int4 q2 = __ldg(P0 + 32 + lane); ((int4*)PRD0)[32 + lane] = q2; h = max4(q2) >= 0; }
            bh0 = __ballot_sync(0xffffffffu, h);
            q = __ldg(P1 + lane); ((int4*)PRD1)[lane] = q;
            bl1 = __ballot_sync(0xffffffffu, max4(q) >= 0);
            h = true;
            if (lane < 16) { int4 q2 = __ldg(P1 + 32 + lane); ((int4*)PRD1)[32 + lane] = q2; h = max4(q2) >= 0; }
            bh1 = __ballot_sync(0xffffffffu, h);
        }

        // ---- stage g_pre tiles, interleaved for MLP ----
        {
            const float4* s0 = (const float4*)(g_pre + (size_t)d0 * (NN * 64));
            const float4* s1 = (const float4*)(g_pre + (size_t)d1 * (NN * 64));
            #pragma unroll
            for (int k = 0; k < 24; k++) {
                ((float4*)OUT0)[lane + 32 * k] = __ldg(s0 + lane + 32 * k);
                ((float4*)OUT1)[lane + 32 * k] = __ldg(s1 + lane + 32 * k);
            }
        }
        __syncwarp();

        // ---- pred-less nodes (t=0 always + rare): single path from gmem ----
        #pragma unroll 1
        for (int e = 0; e < 2; e++) {
            float* OUT = e ? OUT1 : OUT0;
            float* SCB = e ? SCB1 : SCB0;
            const int dd = e ? d1 : d0;
            const unsigned mbl = e ? bl1 : bl0, mbh = e ? bh1 : bh0;
            ull miss = (ull)(~mbl) | ((ull)((~mbh) & 0xffffu) << 32);
            while (miss) {
                int t = __ffsll(miss) - 1;
                miss &= miss - 1;
                const float* ar = atoms + ((size_t)dd * NN + t) * DF;
                float acc0 = a0 ? __ldg(&bs[r0]) : 0.f;
                float acc1 = a1 ? __ldg(&bs[r1]) : 0.f;
                #pragma unroll 31
                for (int f = 0; f < DF; f++) {
                    float xv = __ldg(ar + f);
                    if (a0) acc0 = fmaf(__ldg(&Ws[r0 * DF + f]), xv, acc0);
                    if (a1) acc1 = fmaf(__ldg(&Ws[r1 * DF + f]), xv, acc1);
                }
                float v0 = fmaxf(acc0, 0.f), v1 = fmaxf(acc1, 0.f);
                *(float2*)&OUT[t * 64 + r0] = make_float2(a0 ? v0 : 0.f, a1 ? v1 : 0.f);
                float c = v0 * aw0 + v1 * aw1;
                c = warp_sum(c);
                if (lane < 4) SCB[t * 4 + lane] = (lane == 0) ? c : 0.f;
            }
        }
        __syncwarp();

        // ================= recurrent step loop, 2 streams =================
        for (int t = 1; t < NN; t++) {
            const bool h0 = mbit(bl0, bh0, t);
            const bool h1 = mbit(bl1, bh1, t);

            // ---- phase A: softmax + aggregate -> XS ----
            #pragma unroll
            for (int e = 0; e < 2; e++) {
                if (e ? !h1 : !h0) continue;
                float* OUT = e ? OUT1 : OUT0;
                float* XS  = e ? XS1  : XS0;
                float* SCB = e ? SCB1 : SCB0;
                const int* PRD = e ? PRD1 : PRD0;
                int4 p = ((const int4*)PRD)[t];
                int q0 = max(p.x,0), q1 = max(p.y,0), q2 = max(p.z,0), q3 = max(p.w,0);
                float4 c0 = *(float4*)&SCB[q0*4];
                float4 c1 = *(float4*)&SCB[q1*4];
                float4 c2 = *(float4*)&SCB[q2*4];
                float4 c3 = *(float4*)&SCB[q3*4];
                float s0 = (p.x >= 0) ? (c0.x+c0.y+c0.z+c0.w) : -1e30f;
                float s1 = (p.y >= 0) ? (c1.x+c1.y+c1.z+c1.w) : -1e30f;
                float s2 = (p.z >= 0) ? (c2.x+c2.y+c2.z+c2.w) : -1e30f;
                float s3 = (p.w >= 0) ? (c3.x+c3.y+c3.z+c3.w) : -1e30f;
                float m = fmaxf(fmaxf(s0, s1), fmaxf(s2, s3));
                float e0 = (p.x >= 0) ? __expf(s0 - m) : 0.f;
                float e1 = (p.y >= 0) ? __expf(s1 - m) : 0.f;
                float e2 = (p.z >= 0) ? __expf(s2 - m) : 0.f;
                float e3 = (p.w >= 0) ? __expf(s3 - m) : 0.f;
                float inv = 1.f / (e0 + e1 + e2 + e3);
                float2 u0 = *(float2*)&OUT[q0*64 + r0];
                float2 u1 = *(float2*)&OUT[q1*64 + r0];
                float2 u2 = *(float2*)&OUT[q2*64 + r0];
                float2 u3 = *(float2*)&OUT[q3*64 + r0];
                float x0 = (e0*u0.x + e1*u1.x + e2*u2.x + e3*u3.x) * inv;
                float x1 = (e0*u0.y + e1*u1.y + e2*u2.y + e3*u3.y) * inv;
                *(float2*)&XS[r0] = make_float2(x0, x1);   // lane31 writes zeros
            }
            __syncwarp();

            // ---- phase B: matvec(s) + store + score partials ----
            if (h0 & h1) {
                float2 ap0 = *(float2*)&OUT0[t*64 + r0];
                float2 ap1 = *(float2*)&OUT1[t*64 + r0];
                const ulonglong2* xa = (const ulonglong2*)XS0;
                const ulonglong2* xb = (const ulonglong2*)XS1;
                ull A0=0,A1=0,A2=0,A3=0,B0=0,B1=0,B2=0,B3=0;
                ull C0=0,C1=0,C2=0,C3=0,D0=0,D1=0,D2=0,D3=0;
                #pragma unroll
                for (int i = 0; i < 8; i++) {
                    ulonglong2 u0 = xa[2*i], w0 = xa[2*i + 1];
                    ulonglong2 u1 = xb[2*i], w1 = xb[2*i + 1];
                    A0 = ffma2(W[4*i],      u0.x, A0); A1 = ffma2(W[4*i+1],    u0.y, A1);
                    A2 = ffma2(W[4*i+2],    w0.x, A2); A3 = ffma2(W[4*i+3],    w0.y, A3);
                    B0 = ffma2(W[32+4*i],   u0.x, B0); B1 = ffma2(W[32+4*i+1], u0.y, B1);
                    B2 = ffma2(W[32+4*i+2], w0.x, B2); B3 = ffma2(W[32+4*i+3], w0.y, B3);
                    C0 = ffma2(W[4*i],      u1.x, C0); C1 = ffma2(W[4*i+1],    u1.y, C1);
                    C2 = ffma2(W[4*i+2],    w1.x, C2); C3 = ffma2(W[4*i+3],    w1.y, C3);
                    D0 = ffma2(W[32+4*i],   u1.x, D0); D1 = ffma2(W[32+4*i+1], u1.y, D1);
                    D2 = ffma2(W[32+4*i+2], w1.x, D2); D3 = ffma2(W[32+4*i+3], w1.y, D3);
                }
                float sA = (lo2(A0)+hi2(A0)) + (lo2(A1)+hi2(A1)) + (lo2(A2)+hi2(A2)) + (lo2(A3)+hi2(A3));
                float sB = (lo2(B0)+hi2(B0)) + (lo2(B1)+hi2(B1)) + (lo2(B2)+hi2(B2)) + (lo2(B3)+hi2(B3));
                float sC = (lo2(C0)+hi2(C0)) + (lo2(C1)+hi2(C1)) + (lo2(C2)+hi2(C2)) + (lo2(C3)+hi2(C3));
                float sD = (lo2(D0)+hi2(D0)) + (lo2(D1)+hi2(D1)) + (lo2(D2)+hi2(D2)) + (lo2(D3)+hi2(D3));
                float v00 = fmaxf(sA + ap0.x, 0.f), v01 = fmaxf(sB + ap0.y, 0.f);
                float v10 = fmaxf(sC + ap1.x, 0.f), v11 = fmaxf(sD + ap1.y, 0.f);
                *(float2*)&OUT0[t*64 + r0] = make_float2(a0 ? v00 : 0.f, a1 ? v01 : 0.f);
                *(float2*)&OUT1[t*64 + r0] = make_float2(a0 ? v10 : 0.f, a1 ? v11 : 0.f);
                float c0 = v00 * aw0 + v01 * aw1;
                float c1 = v10 * aw0 + v11 * aw1;
                c0 = red8(c0); c1 = red8(c1);
                if ((lane & 7) == 0) {
                    SCB0[t*4 + (lane >> 3)] = c0;
                    SCB1[t*4 + (lane >> 3)] = c1;
                }
            } else if (h0 | h1) {
                float* OUT = h0 ? OUT0 : OUT1;
                float* XS  = h0 ? XS0  : XS1;
                float* SCB = h0 ? SCB0 : SCB1;
                float2 ap = *(float2*)&OUT[t*64 + r0];
                const ulonglong2* xp = (const ulonglong2*)XS;
                ull A0=0,A1=0,A2=0,A3=0,B0=0,B1=0,B2=0,B3=0;
                #pragma unroll
                for (int i = 0; i < 8; i++) {
                    ulonglong2 u = xp[2*i], w = xp[2*i + 1];
                    A0 = ffma2(W[4*i],      u.x, A0); A1 = ffma2(W[4*i+1],    u.y, A1);
                    A2 = ffma2(W[4*i+2],    w.x, A2); A3 = ffma2(W[4*i+3],    w.y, A3);
                    B0 = ffma2(W[32+4*i],   u.x, B0); B1 = ffma2(W[32+4*i+1], u.y, B1);
                    B2 = ffma2(W[32+4*i+2], w.x, B2); B3 = ffma2(W[32+4*i+3], w.y, B3);
                }
                float sA = (lo2(A0)+hi2(A0)) + (lo2(A1)+hi2(A1)) + (lo2(A2)+hi2(A2)) + (lo2(A3)+hi2(A3));
                float sB = (lo2(B0)+hi2(B0)) + (lo2(B1)+hi2(B1)) + (lo2(B2)+hi2(B2)) + (lo2(B3)+hi2(B3));
                float v0 = fmaxf(sA + ap.x, 0.f), v1 = fmaxf(sB + ap.y, 0.f);
                *(float2*)&OUT[t*64 + r0] = make_float2(a0 ? v0 : 0.f, a1 ? v1 : 0.f);
                float c = v0 * aw0 + v1 * aw1;
                c = red8(c);
                if ((lane & 7) == 0) SCB[t*4 + (lane >> 3)] = c;
            }
            __syncwarp();
        }

        // ---- finalize both dags ----
        {
            float2 l0 = *(float2*)&OUT0[47*64 + r0];
            float2 l1 = *(float2*)&OUT1[47*64 + r0];
            *(float2*)&g_last[(size_t)d0*64 + r0] = l0;
            *(float2*)&g_last[(size_t)d1*64 + r0] = l1;
            const float dg0 = a0 ? __ldg(&dagw[r0]) : 0.f;
            const float dg1 = a1 ? __ldg(&dagw[r1]) : 0.f;
            float v0 = l0.x * dg0 + l0.y * dg1;
            float v1 = l1.x * dg0 + l1.y * dg1;
            v0 = warp_sum(v0); v1 = warp_sum(v1);
            if (lane == 0) { g_score[d0] = v0; g_score[d1] = v1; }
        }
        __syncwarp();
    }
}

// =================================================================
// k_pool_partial: deterministic partial softmax pooling over 64 DAGs
// =================================================================
__global__ void k_pool_partial() {
    __shared__ float sm_e[64];
    __shared__ float sm_red[4];
    int tid = threadIdx.x;        // 128
    int b = blockIdx.x;
    int d0 = b * 64;

    float s = (tid < 64) ? g_score[d0 + tid] : -1e30f;
    float v = s;
    #pragma unroll
    for (int o = 16; o > 0; o >>= 1) v = fmaxf(v, __shfl_xor_sync(0xffffffffu, v, o));
    if ((tid & 31) == 0 && tid < 64) sm_red[tid >> 5] = v;
    __syncthreads();
    float m = fmaxf(sm_red[0], sm_red[1]);

    float e = (tid < 64) ? __expf(s - m) : 0.f;
    if (tid < 64) sm_e[tid] = e;
    float se = warp_sum(e);
    if ((tid & 31) == 0 && tid < 64) sm_red[2 + (tid >> 5)] = se;
    __syncthreads();
    if (tid == 0) { g_partS[b] = sm_red[2] + sm_red[3]; g_partM[b] = m; }
    if (tid < DF) {
        float acc = 0.f;
        #pragma unroll 8
        for (int dd = 0; dd < 64; dd++)
            acc = fmaf(sm_e[dd], g_last[(size_t)(d0 + dd) * 64 + tid], acc);
        g_partP[b * 64 + tid] = acc;
    }
}

// =================================================================
// k_final: combine partials -> pooled -> sigmoid(W_final @ pooled + b)
// =================================================================
__global__ void k_final(const float* __restrict__ Wf, const float* __restrict__ bf,
                        float* __restrict__ out) {
    __shared__ float sw[K2B];
    __shared__ float smMax[16];
    __shared__ float smSum[16];
    __shared__ float smScalar[2];
    __shared__ float part8[8][64];
    __shared__ float pooled[64];
    int tid = threadIdx.x;        // 512
    int lane = tid & 31, warp = tid >> 5;

    float m = (tid < K2B) ? g_partM[tid] : -1e30f;
    float v = m;
    #pragma unroll
    for (int o = 16; o > 0; o >>= 1) v = fmaxf(v, __shfl_xor_sync(0xffffffffu, v, o));
    if (lane == 0) smMax[warp] = v;
    __syncthreads();
    if (tid == 0) {
        float M = smMax[0];
        #pragma unroll
        for (int w = 1; w < 16; w++) M = fmaxf(M, smMax[w]);
        smScalar[0] = M;
    }
    __syncthreads();
    float M = smScalar[0];

    float wb = (tid < K2B) ? __expf(m - M) : 0.f;
    if (tid < K2B) sw[tid] = wb;
    float ss = (tid < K2B) ? g_partS[tid] * wb : 0.f;
    ss = warp_sum(ss);
    if (lane == 0) smSum[warp] = ss;
    __syncthreads();
    if (tid == 0) {
        float S = 0.f;
        #pragma unroll
        for (int w = 0; w < 16; w++) S += smSum[w];
        smScalar[1] = 1.f / S;
    }
    __syncthreads();
    float invS = smScalar[1];

    {
        int grp = tid >> 6, gg = tid & 63;
        float acc = 0.f;
        int b0 = grp * 32;
        #pragma unroll 8
        for (int b2 = b0; b2 < b0 + 32; b2++)
            acc = fmaf(sw[b2], g_partP[b2 * 64 + gg], acc);
        part8[grp][gg] = acc;
    }
    __syncthreads();
    if (tid < DF) {
        float acc = 0.f;
        #pragma unroll
        for (int c = 0; c < 8; c++) acc += part8[c][tid];
        pooled[tid] = acc * invS;
    }
    if (tid >= DF && tid < 64) pooled[tid] = 0.f;
    __syncthreads();

    for (int o = tid; o < NCLS; o += 512) {
        float acc = bf[o];
        #pragma unroll
        for (int gg = 0; gg < DF; gg++) acc = fmaf(Wf[o * DF + gg], pooled[gg], acc);
        out[o] = 1.f / (1.f + __expf(-acc));
    }
}

// =================================================================
extern "C" void kernel_launch(void* const* d_in, const int* in_sizes, int n_in,
                              void* d_out, int out_size) {
    const float* atoms = (const float*)d_in[0];
    const int*   preds = (const int*)  d_in[1];
    const float* Ws    = (const float*)d_in[2];
    const float* bs    = (const float*)d_in[3];
    const float* Wm    = (const float*)d_in[4];
    const float* bm    = (const float*)d_in[5];
    const float* attw  = (const float*)d_in[6];
    const float* dagw  = (const float*)d_in[7];
    const float* Wf    = (const float*)d_in[8];
    const float* bf    = (const float*)d_in[9];
    float* out = (float*)d_out;

    cudaFuncSetAttribute(k_dag, cudaFuncAttributeMaxDynamicSharedMemorySize, DSM_BYTES);

    k_zero<<<1, 1>>>();
    k_pre<<<(N_DAGS * NN) / 256, 128>>>(atoms, Wm, bm);
    k_dag<<<296, 128, DSM_BYTES>>>(atoms, preds, Wm, Ws, bs, attw, dagw);
    k_pool_partial<<<K2B, 128>>>();
    k_final<<<1, 512>>>(Wf, bf, out);
}

// round 17
// speedup vs baseline: 1.0321x; 1.0321x over previous
#include <cuda_runtime.h>
#include <cuda_bf16.h>
#include <cstdint>

#define N_DAGS 16384
#define NN     48
#define DF     62
#define NCLS   500
#define K2B    256

typedef unsigned long long ull;

// ---------------- scratch ----------------
__device__ float g_pre [(size_t)N_DAGS * NN * 64];   // atomP + b_merge, 64-padded
__device__ unsigned char g_ord[(size_t)N_DAGS * 128]; // per-dag schedule
__device__ float g_last [N_DAGS * 64];
__device__ float g_score[N_DAGS];
__device__ float g_partP[K2B * 64];
__device__ float g_partS[K2B];
__device__ float g_partM[K2B];
__device__ unsigned g_ctr;

// ---------------- packed f32x2 helpers ----------------
__device__ __forceinline__ ull ffma2(ull a, ull b, ull c) {
    ull d;
    asm("fma.rn.f32x2 %0, %1, %2, %3;" : "=l"(d) : "l"(a), "l"(b), "l"(c));
    return d;
}
__device__ __forceinline__ ull pack2(float a, float b) {
    return (ull)__float_as_uint(a) | ((ull)__float_as_uint(b) << 32);
}
__device__ __forceinline__ float lo2(ull v) { return __uint_as_float((unsigned)v); }
__device__ __forceinline__ float hi2(ull v) { return __uint_as_float((unsigned)(v >> 32)); }

__device__ __forceinline__ float warp_sum(float v) {
    #pragma unroll
    for (int o = 16; o > 0; o >>= 1) v += __shfl_xor_sync(0xffffffffu, v, o);
    return v;
}
__device__ __forceinline__ float red8(float v) {
    v += __shfl_xor_sync(0xffffffffu, v, 4);
    v += __shfl_xor_sync(0xffffffffu, v, 2);
    v += __shfl_xor_sync(0xffffffffu, v, 1);
    return v;
}
__device__ __forceinline__ int max4(int4 q) { return max(max(q.x, q.y), max(q.z, q.w)); }

// ---------------- mma helpers (bf16 m16n8k16) ----------------
__device__ __forceinline__ uint32_t smem_u32(const void* p) {
    return (uint32_t)__cvta_generic_to_shared(p);
}
__device__ __forceinline__ void ldm_x4(unsigned r[4], uint32_t addr) {
    asm volatile("ldmatrix.sync.aligned.m8n8.x4.shared.b16 {%0,%1,%2,%3}, [%4];"
        : "=r"(r[0]), "=r"(r[1]), "=r"(r[2]), "=r"(r[3]) : "r"(addr));
}
__device__ __forceinline__ void ldm_x2t(unsigned r[2], uint32_t addr) {
    asm volatile("ldmatrix.sync.aligned.m8n8.x2.trans.shared.b16 {%0,%1}, [%2];"
        : "=r"(r[0]), "=r"(r[1]) : "r"(addr));
}
__device__ __forceinline__ void mma16816(float d[4], const unsigned a[4], const unsigned b[2]) {
    asm volatile("mma.sync.aligned.m16n8k16.row.col.f32.bf16.bf16.f32 "
        "{%0,%1,%2,%3}, {%4,%5,%6,%7}, {%8,%9}, {%0,%1,%2,%3};"
        : "+f"(d[0]), "+f"(d[1]), "+f"(d[2]), "+f"(d[3])
        : "r"(a[0]), "r"(a[1]), "r"(a[2]), "r"(a[3]), "r"(b[0]), "r"(b[1]));
}

// =================================================================
// k_zero: reset the work-stealing counter
// =================================================================
__global__ void k_zero() { g_ctr = 0u; }

// =================================================================
// k_sched: per-dag wave schedule. 1 thread = 1 dag.
// depth(t) = 0 if pred-less else 1 + max depth(preds).
// Output (128 B/dag): [0..n) node ids sorted by depth (depth>=1 only),
// [48] = n_chunks, [49..) = chunk lengths (waves split into <=4).
// =================================================================
__global__ void __launch_bounds__(128)
k_sched(const int* __restrict__ preds) {
    const int d = blockIdx.x * 128 + threadIdx.x;
    if (d >= N_DAGS) return;
    signed char depth[NN];
    unsigned char cnt[NN];
    #pragma unroll
    for (int i = 0; i < NN; i++) cnt[i] = 0;
    const int4* P = (const int4*)preds + (size_t)d * NN;
    int maxd = 0;
    for (int t = 0; t < NN; t++) {
        int4 q = __ldg(P + t);
        int dd = -1;
        if (q.x >= 0) dd = max(dd, (int)depth[q.x]);
        if (q.y >= 0) dd = max(dd, (int)depth[q.y]);
        if (q.z >= 0) dd = max(dd, (int)depth[q.z]);
        if (q.w >= 0) dd = max(dd, (int)depth[q.w]);
        dd += 1;
        depth[t] = (signed char)dd;
        cnt[dd]++;
        maxd = max(maxd, dd);
    }
    unsigned char fill[NN];
    {
        int pos = 0;
        for (int dd = 1; dd <= maxd; dd++) { fill[dd] = (unsigned char)pos; pos += cnt[dd]; }
    }
    unsigned char ord[NN];
    for (int t = 0; t < NN; t++) {
        int dd = depth[t];
        if (dd > 0) ord[fill[dd]++] = (unsigned char)t;
    }
    unsigned char* O = g_ord + (size_t)d * 128;
    int n = 0;
    for (int dd = 1; dd <= maxd; dd++) n += cnt[dd];
    for (int i = 0; i < n; i++) O[i] = ord[i];
    int nc = 0;
    for (int dd = 1; dd <= maxd; dd++) {
        int sz = cnt[dd];
        while (sz > 0) { int c = min(sz, 4); O[49 + nc] = (unsigned char)c; nc++; sz -= c; }
    }
    O[48] = (unsigned char)nc;
}

// =================================================================
// k_pre: g_pre[node][g] = sum_f Wm[g][62+f]*atoms[node][f] + bm[g]
// Split-bf16 3-product GEMM. 4 row-tiles per block (W staged once).
// =================================================================
#define PSTRIDE 72

__global__ void __launch_bounds__(128)
k_pre(const float* __restrict__ atoms, const float* __restrict__ Wm,
      const float* __restrict__ bm) {
    __shared__ __align__(16) __nv_bfloat16 sAh[64 * PSTRIDE];
    __shared__ __align__(16) __nv_bfloat16 sAl[64 * PSTRIDE];
    __shared__ __align__(16) __nv_bfloat16 sWh[64 * PSTRIDE];
    __shared__ __align__(16) __nv_bfloat16 sWl[64 * PSTRIDE];
    __shared__ float sBm[64];

    const int tid = threadIdx.x, lane = tid & 31, warp = tid >> 5;

    for (int i = tid; i < 64 * 64; i += 128) {
        int f = i >> 6, g = i & 63;
        float w = (f < DF && g < DF) ? __ldg(&Wm[g * 124 + DF + f]) : 0.f;
        __nv_bfloat16 h = __float2bfloat16(w);
        sWh[f * PSTRIDE + g] = h;
        sWl[f * PSTRIDE + g] = __float2bfloat16(w - __bfloat162float(h));
    }
    if (tid < 64) sBm[tid] = (tid < DF) ? __ldg(&bm[tid]) : 0.f;

    #pragma unroll 1
    for (int tile = 0; tile < 4; tile++) {
        const size_t row0 = (size_t)blockIdx.x * 256 + (size_t)tile * 64;
        __syncthreads();

        for (int i = tid; i < 64 * 64; i += 128) {
            int r = i >> 6, c = i & 63;
            float a = (c < DF) ? __ldg(&atoms[(row0 + r) * DF + c]) : 0.f;
            __nv_bfloat16 h = __float2bfloat16(a);
            sAh[r * PSTRIDE + c] = h;
            sAl[r * PSTRIDE + c] = __float2bfloat16(a - __bfloat162float(h));
        }
        __syncthreads();

        unsigned ah[4][4], al[4][4];
        {
            uint32_t aoff = ((warp * 16 + (lane & 15)) * PSTRIDE) * 2 + (lane >> 4) * 16;
            uint32_t aH = smem_u32(sAh) + aoff, aL = smem_u32(sAl) + aoff;
            #pragma unroll
            for (int k = 0; k < 4; k++) {
                ldm_x4(ah[k], aH + k * 32);
                ldm_x4(al[k], aL + k * 32);
            }
        }

        const uint32_t bRow = (lane & 15) * (PSTRIDE * 2);
        #pragma unroll
        for (int n = 0; n < 8; n++) {
            float d[4] = {0.f, 0.f, 0.f, 0.f};
            #pragma unroll
            for (int k = 0; k < 4; k++) {
                unsigned bh[2], blo[2];
                uint32_t boff = (uint32_t)(k * 16 * PSTRIDE * 2) + bRow + n * 16;
                ldm_x2t(bh,  smem_u32(sWh) + boff);
                ldm_x2t(blo, smem_u32(sWl) + boff);
                mma16816(d, ah[k], bh);
                mma16816(d, al[k], bh);
                mma16816(d, ah[k], blo);
            }
            int r = lane >> 2;
            int c = n * 8 + 2 * (lane & 3);
            float b0 = sBm[c], b1 = sBm[c + 1];
            size_t ro = (row0 + warp * 16 + r) * 64 + c;
            *(float2*)&g_pre[ro]           = make_float2(d[0] + b0, d[1] + b1);
            *(float2*)&g_pre[ro + 8 * 64]  = make_float2(d[2] + b0, d[3] + b1);
        }
    }
}

// per-warp smem region: 3744 floats (14976 B)
#define RWF    3744
#define W_OUT  0
#define W_XS   3072          // 4 slots x 64
#define W_SCB  3328
#define W_PRD  3520
#define W_ORD  3712          // 128 B schedule
#define DSM_BYTES (4 * RWF * 4)   // 59904

// =================================================================
// k_dag: recurrent loop in WAVE CHUNKS (<=4 independent nodes).
// ONE WARP = ONE DAG, dynamic work-stealing. Thread owns rows (2l,2l+1);
// x-half merge weights in regs. 2 syncwarps per chunk (~15 chunks).
// =================================================================
__global__ void __launch_bounds__(128, 3)
k_dag(const float* __restrict__ atoms, const int* __restrict__ preds,
      const float* __restrict__ Wm,   const float* __restrict__ Ws,
      const float* __restrict__ bs,   const float* __restrict__ attw,
      const float* __restrict__ dagw) {
    extern __shared__ float DSM[];
    const int tid = threadIdx.x, lane = tid & 31, warp = tid >> 5;
    float* R   = DSM + warp * RWF;
    float* OUT = R + W_OUT;
    float* XS  = R + W_XS;
    float* SCB = R + W_SCB;
    int*   PRD = (int*)(R + W_PRD);
    const unsigned char* ORDb = (const unsigned char*)(R + W_ORD);

    const int r0 = 2 * lane, r1 = 2 * lane + 1;
    const bool a0 = (r0 < DF), a1 = (r1 < DF);
    const float aw0 = a0 ? attw[r0] : 0.f, aw1 = a1 ? attw[r1] : 0.f;

    // x-half merge weights: loaded once
    ull W[64];
    #pragma unroll
    for (int j = 0; j < 32; j++) {
        W[j]      = (a0 && j < 31) ? pack2(__ldg(&Wm[r0*124 + 2*j]), __ldg(&Wm[r0*124 + 2*j + 1])) : 0ull;
        W[32 + j] = (a1 && j < 31) ? pack2(__ldg(&Wm[r1*124 + 2*j]), __ldg(&Wm[r1*124 + 2*j + 1])) : 0ull;
    }

    #pragma unroll 1
    for (;;) {
        // ---- dynamic ticket ----
        int d;
        if (lane == 0) d = (int)atomicAdd(&g_ctr, 1u);
        d = __shfl_sync(0xffffffffu, d, 0);
        if (d >= N_DAGS) break;

        // ---- preds + pred-less mask ----
        unsigned bl, bh;
        {
            const int4* P = (const int4*)(preds + (size_t)d * NN * 4);
            int4 q = __ldg(P + lane); ((int4*)PRD)[lane] = q;
            bl = __ballot_sync(0xffffffffu, max4(q) >= 0);
            bool h = true;
            if (lane < 16) { int4 q2 = __ldg(P + 32 + lane); ((int4*)PRD)[32 + lane] = q2; h = max4(q2) >= 0; }
            bh = __ballot_sync(0xffffffffu, h);
        }

        // ---- stage g_pre tile + schedule ----
        {
            const float4* src = (const float4*)(g_pre + (size_t)d * (NN * 64));
            #pragma unroll
            for (int k = 0; k < 24; k++)
                ((float4*)OUT)[lane + 32 * k] = __ldg(src + lane + 32 * k);
            if (lane < 8)
                ((int4*)(R + W_ORD))[lane] = __ldg((const int4*)(g_ord + (size_t)d * 128) + lane);
        }
        __syncwarp();

        // ---- pred-less nodes (depth 0): single path from gmem ----
        {
            ull miss = (ull)(~bl) | ((ull)((~bh) & 0xffffu) << 32);
            while (miss) {
                int t = __ffsll(miss) - 1;
                miss &= miss - 1;
                const float* ar = atoms + ((size_t)d * NN + t) * DF;
                float acc0 = a0 ? __ldg(&bs[r0]) : 0.f;
                float acc1 = a1 ? __ldg(&bs[r1]) : 0.f;
                #pragma unroll 31
                for (int f = 0; f < DF; f++) {
                    float xv = __ldg(ar + f);
                    if (a0) acc0 = fmaf(__ldg(&Ws[r0 * DF + f]), xv, acc0);
                    if (a1) acc1 = fmaf(__ldg(&Ws[r1 * DF + f]), xv, acc1);
                }
                float v0 = fmaxf(acc0, 0.f), v1 = fmaxf(acc1, 0.f);
                *(float2*)&OUT[t * 64 + r0] = make_float2(a0 ? v0 : 0.f, a1 ? v1 : 0.f);
                float c = v0 * aw0 + v1 * aw1;
                c = warp_sum(c);
                if (lane < 4) SCB[t * 4 + lane] = (lane == 0) ? c : 0.f;
            }
        }
        __syncwarp();

        // ================= wave-chunk loop =================
        const int nchunks = ORDb[48];
        int pos = 0;
        #pragma unroll 1
        for (int c = 0; c < nchunks; c++) {
            const int len = ORDb[49 + c];

            // ---- phase A: all chunk nodes (independent) -> XS slots ----
            #pragma unroll 1
            for (int i = 0; i < len; i++) {
                const int t = ORDb[pos + i];
                int4 p = ((const int4*)PRD)[t];
                int q0 = max(p.x,0), q1 = max(p.y,0), q2 = max(p.z,0), q3 = max(p.w,0);
                float4 c0 = *(float4*)&SCB[q0*4];
                float4 c1 = *(float4*)&SCB[q1*4];
                float4 c2 = *(float4*)&SCB[q2*4];
                float4 c3 = *(float4*)&SCB[q3*4];
                float s0 = (p.x >= 0) ? (c0.x+c0.y+c0.z+c0.w) : -1e30f;
                float s1 = (p.y >= 0) ? (c1.x+c1.y+c1.z+c1.w) : -1e30f;
                float s2 = (p.z >= 0) ? (c2.x+c2.y+c2.z+c2.w) : -1e30f;
                float s3 = (p.w >= 0) ? (c3.x+c3.y+c3.z+c3.w) : -1e30f;
                float m = fmaxf(fmaxf(s0, s1), fmaxf(s2, s3));
                float e0 = (p.x >= 0) ? __expf(s0 - m) : 0.f;
                float e1 = (p.y >= 0) ? __expf(s1 - m) : 0.f;
                float e2 = (p.z >= 0) ? __expf(s2 - m) : 0.f;
                float e3 = (p.w >= 0) ? __expf(s3 - m) : 0.f;
                float inv = 1.f / (e0 + e1 + e2 + e3);
                float2 u0 = *(float2*)&OUT[q0*64 + r0];
                float2 u1 = *(float2*)&OUT[q1*64 + r0];
                float2 u2 = *(float2*)&OUT[q2*64 + r0];
                float2 u3 = *(float2*)&OUT[q3*64 + r0];
                float x0 = (e0*u0.x + e1*u1.x + e2*u2.x + e3*u3.x) * inv;
                float x1 = (e0*u0.y + e1*u1.y + e2*u2.y + e3*u3.y) * inv;
                *(float2*)&XS[i * 64 + r0] = make_float2(x0, x1);   // lane31 writes zeros
            }
            __syncwarp();

            // ---- phase B: matvec per chunk node ----
            #pragma unroll 1
            for (int i = 0; i < len; i++) {
                const int t = ORDb[pos + i];
                float2 ap = *(float2*)&OUT[t*64 + r0];
                const ulonglong2* xp = (const ulonglong2*)(XS + i * 64);
                ull A0=0,A1=0,A2=0,A3=0,B0=0,B1=0,B2=0,B3=0;
                #pragma unroll
                for (int k = 0; k < 8; k++) {
                    ulonglong2 u = xp[2*k], w = xp[2*k + 1];
                    A0 = ffma2(W[4*k],      u.x, A0); A1 = ffma2(W[4*k+1],    u.y, A1);
                    A2 = ffma2(W[4*k+2],    w.x, A2); A3 = ffma2(W[4*k+3],    w.y, A3);
                    B0 = ffma2(W[32+4*k],   u.x, B0); B1 = ffma2(W[32+4*k+1], u.y, B1);
                    B2 = ffma2(W[32+4*k+2], w.x, B2); B3 = ffma2(W[32+4*k+3], w.y, B3);
                }
                float sA = (lo2(A0)+hi2(A0)) + (lo2(A1)+hi2(A1)) + (lo2(A2)+hi2(A2)) + (lo2(A3)+hi2(A3));
                float sB = (lo2(B0)+hi2(B0)) + (lo2(B1)+hi2(B1)) + (lo2(B2)+hi2(B2)) + (lo2(B3)+hi2(B3));
                float v0 = fmaxf(sA + ap.x, 0.f), v1 = fmaxf(sB + ap.y, 0.f);
                *(float2*)&OUT[t*64 + r0] = make_float2(a0 ? v0 : 0.f, a1 ? v1 : 0.f);
                float cc = v0 * aw0 + v1 * aw1;
                cc = red8(cc);
                if ((lane & 7) == 0) SCB[t*4 + (lane >> 3)] = cc;
            }
            __syncwarp();
            pos += len;
        }

        // ---- finalize DAG ----
        {
            float2 last = *(float2*)&OUT[47*64 + r0];
            *(float2*)&g_last[(size_t)d*64 + r0] = last;
            const float dg0 = a0 ? __ldg(&dagw[r0]) : 0.f;
            const float dg1 = a1 ? __ldg(&dagw[r1]) : 0.f;
            float v = last.x * dg0 + last.y * dg1;
            v = warp_sum(v);
            if (lane == 0) g_score[d] = v;
        }
        __syncwarp();
    }
}

// =================================================================
// k_pool_partial: deterministic partial softmax pooling over 64 DAGs
// =================================================================
__global__ void k_pool_partial() {
    __shared__ float sm_e[64];
    __shared__ float sm_red[4];
    int tid = threadIdx.x;        // 128
    int b = blockIdx.x;
    int d0 = b * 64;

    float s = (tid < 64) ? g_score[d0 + tid] : -1e30f;
    float v = s;
    #pragma unroll
    for (int o = 16; o > 0; o >>= 1) v = fmaxf(v, __shfl_xor_sync(0xffffffffu, v, o));
    if ((tid & 31) == 0 && tid < 64) sm_red[tid >> 5] = v;
    __syncthreads();
    float m = fmaxf(sm_red[0], sm_red[1]);

    float e = (tid < 64) ? __expf(s - m) : 0.f;
    if (tid < 64) sm_e[tid] = e;
    float se = warp_sum(e);
    if ((tid & 31) == 0 && tid < 64) sm_red[2 + (tid >> 5)] = se;
    __syncthreads();
    if (tid == 0) { g_partS[b] = sm_red[2] + sm_red[3]; g_partM[b] = m; }
    if (tid < DF) {
        float acc = 0.f;
        #pragma unroll 8
        for (int dd = 0; dd < 64; dd++)
            acc = fmaf(sm_e[dd], g_last[(size_t)(d0 + dd) * 64 + tid], acc);
        g_partP[b * 64 + tid] = acc;
    }
}

// =================================================================
// k_final: combine partials -> pooled -> sigmoid(W_final @ pooled + b)
// =================================================================
__global__ void k_final(const float* __restrict__ Wf, const float* __restrict__ bf,
                        float* __restrict__ out) {
    __shared__ float sw[K2B];
    __shared__ float smMax[16];
    __shared__ float smSum[16];
    __shared__ float smScalar[2];
    __shared__ float part8[8][64];
    __shared__ float pooled[64];
    int tid = threadIdx.x;        // 512
    int lane = tid & 31, warp = tid >> 5;

    float m = (tid < K2B) ? g_partM[tid] : -1e30f;
    float v = m;
    #pragma unroll
    for (int o = 16; o > 0; o >>= 1) v = fmaxf(v, __shfl_xor_sync(0xffffffffu, v, o));
    if (lane == 0) smMax[warp] = v;
    __syncthreads();
    if (tid == 0) {
        float M = smMax[0];
        #pragma unroll
        for (int w = 1; w < 16; w++) M = fmaxf(M, smMax[w]);
        smScalar[0] = M;
    }
    __syncthreads();
    float M = smScalar[0];

    float wb = (tid < K2B) ? __expf(m - M) : 0.f;
    if (tid < K2B) sw[tid] = wb;
    float ss = (tid < K2B) ? g_partS[tid] * wb : 0.f;
    ss = warp_sum(ss);
    if (lane == 0) smSum[warp] = ss;
    __syncthreads();
    if (tid == 0) {
        float S = 0.f;
        #pragma unroll
        for (int w = 0; w < 16; w++) S += smSum[w];
        smScalar[1] = 1.f / S;
    }
    __syncthreads();
    float invS = smScalar[1];

    {
        int grp = tid >> 6, gg = tid & 63;
        float acc = 0.f;
        int b0 = grp * 32;
        #pragma unroll 8
        for (int b2 = b0; b2 < b0 + 32; b2++)
            acc = fmaf(sw[b2], g_partP[b2 * 64 + gg], acc);
        part8[grp][gg] = acc;
    }
    __syncthreads();
    if (tid < DF) {
        float acc = 0.f;
        #pragma unroll
        for (int c = 0; c < 8; c++) acc += part8[c][tid];
        pooled[tid] = acc * invS;
    }
    if (tid >= DF && tid < 64) pooled[tid] = 0.f;
    __syncthreads();

    for (int o = tid; o < NCLS; o += 512) {
        float acc = bf[o];
        #pragma unroll
        for (int gg = 0; gg < DF; gg++) acc = fmaf(Wf[o * DF + gg], pooled[gg], acc);
        out[o] = 1.f / (1.f + __expf(-acc));
    }
}

// =================================================================
extern "C" void kernel_launch(void* const* d_in, const int* in_sizes, int n_in,
                              void* d_out, int out_size) {
    const float* atoms = (const float*)d_in[0];
    const int*   preds = (const int*)  d_in[1];
    const float* Ws    = (const float*)d_in[2];
    const float* bs    = (const float*)d_in[3];
    const float* Wm    = (const float*)d_in[4];
    const float* bm    = (const float*)d_in[5];
    const float* attw  = (const float*)d_in[6];
    const float* dagw  = (const float*)d_in[7];
    const float* Wf    = (const float*)d_in[8];
    const float* bf    = (const float*)d_in[9];
    float* out = (float*)d_out;

    cudaFuncSetAttribute(k_dag, cudaFuncAttributeMaxDynamicSharedMemorySize, DSM_BYTES);

    k_zero<<<1, 1>>>();
    k_sched<<<N_DAGS / 128, 128>>>(preds);
    k_pre<<<(N_DAGS * NN) / 256, 128>>>(atoms, Wm, bm);
    k_dag<<<444, 128, DSM_BYTES>>>(atoms, preds, Wm, Ws, bs, attw, dagw);
    k_pool_partial<<<K2B, 128>>>();
    k_final<<<1, 512>>>(Wf, bf, out);
}